// round 1
// baseline (speedup 1.0000x reference)
#include <cuda_runtime.h>
#include <cstdint>
#include <math.h>

// Problem constants (fixed by the dataset)
#define TOKENS   16384
#define KDIM     2048
#define NEXP     64
#define TM       128     // tokens per block
#define KT       32      // K-chunk staged in smem
#define NCHUNK   (KDIM / KT)
#define XS_LD    132     // padded leading dim for xs[k][token]
#define WS_LD    68      // padded leading dim for ws[k][expert]

typedef unsigned long long ull;

__device__ __forceinline__ ull pack2(float lo, float hi) {
    ull r;
    asm("mov.b64 %0, {%1, %2};" : "=l"(r) : "f"(lo), "f"(hi));
    return r;
}
__device__ __forceinline__ void unpack2(ull v, float& lo, float& hi) {
    asm("mov.b64 {%0, %1}, %2;" : "=f"(lo), "=f"(hi) : "l"(v));
}
// Packed dual-fp32 FMA: d = a*b + d  (fma.rn.f32x2 — 2x FFMA throughput vs 3-reg FFMA)
__device__ __forceinline__ void ffma2(ull& d, ull a, ull b) {
    asm("fma.rn.f32x2 %0, %1, %2, %0;" : "+l"(d) : "l"(a), "l"(b));
}

__global__ __launch_bounds__(256, 1)
void topk_router_kernel(const float* __restrict__ x,
                        const float* __restrict__ W,
                        const float* __restrict__ b,
                        float* __restrict__ out)
{
    // Load tiles (transposed) and the logit staging buffer share storage:
    // load region is dead once the final compute chunk finishes.
    __shared__ union {
        struct {
            float xs[KT][XS_LD];   // xs[k][token]   (128 tokens used)
            float ws[KT][WS_LD];   // ws[k][expert]  (64 experts used)
        } ld;
        float ls[TM][NEXP + 1];    // logits staging, pad to kill bank conflicts
    } sm;
    __shared__ float bsm[NEXP];

    const int tid = threadIdx.x;
    const int tx  = tid & 15;       // token-tile  (8 tokens each)
    const int ty  = tid >> 4;       // expert-tile (4 experts each)
    const int tokBase = blockIdx.x * TM;

    if (tid < NEXP) bsm[tid] = b[tid];

    // 8 tokens x 4 experts accumulators, experts packed as f32x2 pairs
    ull acc[8][2];
#pragma unroll
    for (int i = 0; i < 8; i++) { acc[i][0] = 0ull; acc[i][1] = 0ull; }

    // Register prefetch buffers (one chunk ahead; 6 independent LDG.128/thread)
    float4 px[4];
    float4 pw[2];

    // ---- load chunk 0 into registers ----
#pragma unroll
    for (int r = 0; r < 4; r++) {
        int s = tid + 256 * r;          // float4 slot: token = s>>3, k4 = s&7
        int tok = s >> 3, k4 = s & 7;
        px[r] = *(const float4*)(x + (size_t)(tokBase + tok) * KDIM + k4 * 4);
    }
#pragma unroll
    for (int r = 0; r < 2; r++) {
        int s = tid + 256 * r;          // e = s>>3, k4 = s&7
        int e = s >> 3, k4 = s & 7;
        pw[r] = *(const float4*)(W + (size_t)e * KDIM + k4 * 4);
    }

    // ---- store chunk 0 to smem (transposed) ----
#pragma unroll
    for (int r = 0; r < 4; r++) {
        int s = tid + 256 * r;
        int tok = s >> 3, k4 = s & 7;
        sm.ld.xs[k4 * 4 + 0][tok] = px[r].x;
        sm.ld.xs[k4 * 4 + 1][tok] = px[r].y;
        sm.ld.xs[k4 * 4 + 2][tok] = px[r].z;
        sm.ld.xs[k4 * 4 + 3][tok] = px[r].w;
    }
#pragma unroll
    for (int r = 0; r < 2; r++) {
        int s = tid + 256 * r;
        int e = s >> 3, k4 = s & 7;
        sm.ld.ws[k4 * 4 + 0][e] = pw[r].x;
        sm.ld.ws[k4 * 4 + 1][e] = pw[r].y;
        sm.ld.ws[k4 * 4 + 2][e] = pw[r].z;
        sm.ld.ws[k4 * 4 + 3][e] = pw[r].w;
    }
    __syncthreads();

    // ---- main K loop ----
    for (int c = 0; c < NCHUNK; c++) {
        // prefetch next chunk into registers (overlaps with compute below)
        if (c + 1 < NCHUNK) {
            const int kOff = (c + 1) * KT;
#pragma unroll
            for (int r = 0; r < 4; r++) {
                int s = tid + 256 * r;
                int tok = s >> 3, k4 = s & 7;
                px[r] = *(const float4*)(x + (size_t)(tokBase + tok) * KDIM + kOff + k4 * 4);
            }
#pragma unroll
            for (int r = 0; r < 2; r++) {
                int s = tid + 256 * r;
                int e = s >> 3, k4 = s & 7;
                pw[r] = *(const float4*)(W + (size_t)e * KDIM + kOff + k4 * 4);
            }
        }

#pragma unroll
        for (int k = 0; k < KT; k++) {
            const float4 xa = *(const float4*)&sm.ld.xs[k][tx * 8];
            const float4 xb = *(const float4*)&sm.ld.xs[k][tx * 8 + 4];
            const float4 wv = *(const float4*)&sm.ld.ws[k][ty * 4];
            const ull w01 = pack2(wv.x, wv.y);
            const ull w23 = pack2(wv.z, wv.w);
            const float xv[8] = {xa.x, xa.y, xa.z, xa.w, xb.x, xb.y, xb.z, xb.w};
#pragma unroll
            for (int i = 0; i < 8; i++) {
                const ull xx = pack2(xv[i], xv[i]);
                ffma2(acc[i][0], xx, w01);
                ffma2(acc[i][1], xx, w23);
            }
        }
        __syncthreads();

        if (c + 1 < NCHUNK) {
#pragma unroll
            for (int r = 0; r < 4; r++) {
                int s = tid + 256 * r;
                int tok = s >> 3, k4 = s & 7;
                sm.ld.xs[k4 * 4 + 0][tok] = px[r].x;
                sm.ld.xs[k4 * 4 + 1][tok] = px[r].y;
                sm.ld.xs[k4 * 4 + 2][tok] = px[r].z;
                sm.ld.xs[k4 * 4 + 3][tok] = px[r].w;
            }
#pragma unroll
            for (int r = 0; r < 2; r++) {
                int s = tid + 256 * r;
                int e = s >> 3, k4 = s & 7;
                sm.ld.ws[k4 * 4 + 0][e] = pw[r].x;
                sm.ld.ws[k4 * 4 + 1][e] = pw[r].y;
                sm.ld.ws[k4 * 4 + 2][e] = pw[r].z;
                sm.ld.ws[k4 * 4 + 3][e] = pw[r].w;
            }
            __syncthreads();
        }
    }

    // ---- epilogue: stage logits (+bias) into smem ----
    // (load region is dead now; the union is safe after the last __syncthreads)
#pragma unroll
    for (int i = 0; i < 8; i++) {
        float v0, v1, v2, v3;
        unpack2(acc[i][0], v0, v1);
        unpack2(acc[i][1], v2, v3);
        const int t = tx * 8 + i;
        const int e = ty * 4;
        sm.ls[t][e + 0] = v0 + bsm[e + 0];
        sm.ls[t][e + 1] = v1 + bsm[e + 1];
        sm.ls[t][e + 2] = v2 + bsm[e + 2];
        sm.ls[t][e + 3] = v3 + bsm[e + 3];
    }
    __syncthreads();

    // Output layout (float32): [probs 16384*2][indices 16384*2][logits 16384*64]
    float* probs_out  = out;
    float* idx_out    = out + (size_t)TOKENS * 2;
    float* logits_out = out + (size_t)TOKENS * 4;

    // coalesced logits store: 2048 float4 per block, 8 per thread
#pragma unroll
    for (int r = 0; r < 8; r++) {
        int s  = tid + 256 * r;         // float4 slot: token = s>>4, e4 = s&15
        int t  = s >> 4;
        int e4 = s & 15;
        float4 v = make_float4(sm.ls[t][e4 * 4 + 0], sm.ls[t][e4 * 4 + 1],
                               sm.ls[t][e4 * 4 + 2], sm.ls[t][e4 * 4 + 3]);
        *(float4*)(logits_out + (size_t)(tokBase + t) * NEXP + e4 * 4) = v;
    }

    // top-2 + softmax: one thread per token (pad-65 => conflict-free column reads)
    if (tid < TM) {
        const int t = tid;
        float m1 = -INFINITY, m2 = -INFINITY;
        int   i1 = 0, i2 = 0;
#pragma unroll
        for (int e = 0; e < NEXP; e++) {
            const float v = sm.ls[t][e];
            if (v > m1)      { m2 = m1; i2 = i1; m1 = v; i1 = e; }  // strict >: jax tie-break (first index)
            else if (v > m2) { m2 = v; i2 = e; }
        }
        const float ex = expf(m2 - m1);
        const float inv = 1.0f / (1.0f + ex);
        const int gt = tokBase + t;
        probs_out[gt * 2 + 0] = inv;
        probs_out[gt * 2 + 1] = ex * inv;
        idx_out[gt * 2 + 0] = (float)i1;
        idx_out[gt * 2 + 1] = (float)i2;
    }
}

extern "C" void kernel_launch(void* const* d_in, const int* in_sizes, int n_in,
                              void* d_out, int out_size)
{
    const float* x = (const float*)d_in[0];
    const float* W = (const float*)d_in[1];
    const float* b = (const float*)d_in[2];
    float* out = (float*)d_out;
    topk_router_kernel<<<TOKENS / TM, 256>>>(x, W, b, out);
}

// round 4
// speedup vs baseline: 1.6205x; 1.6205x over previous
#include <cuda_runtime.h>
#include <cstdint>
#include <math.h>

#define TOKENS 16384
#define KDIM   2048
#define NEXP   64
#define TM     128
#define KC     64                      // K elems per chunk
#define NCHUNK (KDIM / KC)             // 32
#define SA     144                     // smem row stride in bytes (72 bf16): conflict-free
#define OFF_AH 0
#define OFF_AL (128 * SA)              // 18432
#define OFF_BH (2 * 128 * SA)          // 36864
#define OFF_BL (2 * 128 * SA + 64 * SA)// 46080
#define DYN_SMEM (2 * 128 * SA + 2 * 64 * SA)  // 55296
#define RESCUE_TH 3e-4f

typedef unsigned int u32;

// Pre-split W planes (bf16 pairs packed in u32), written by prep kernel each call.
__device__ __align__(16) u32 g_Whi[NEXP * KDIM / 2];
__device__ __align__(16) u32 g_Wlo[NEXP * KDIM / 2];

// ---------------- helpers ----------------
static __device__ __forceinline__ u32 smem_u32(const void* p) {
    u32 a;
    asm("{ .reg .u64 t; cvta.to.shared.u64 t, %1; cvt.u32.u64 %0, t; }" : "=r"(a) : "l"(p));
    return a;
}
// pack two f32 -> bf16x2 (low half = f0)
static __device__ __forceinline__ u32 cvt_bf2(float f0, float f1) {
    u32 r;
    asm("cvt.rn.bf16x2.f32 %0, %1, %2;" : "=r"(r) : "f"(f1), "f"(f0));
    return r;
}
static __device__ __forceinline__ void sts64(u32 a, u32 lo, u32 hi) {
    asm volatile("st.shared.v2.b32 [%0], {%1,%2};" :: "r"(a), "r"(lo), "r"(hi) : "memory");
}
static __device__ __forceinline__ void sts128(u32 a, uint4 v) {
    asm volatile("st.shared.v4.b32 [%0], {%1,%2,%3,%4};" :: "r"(a), "r"(v.x), "r"(v.y), "r"(v.z), "r"(v.w) : "memory");
}
static __device__ __forceinline__ void ldm_x4(u32* r, u32 a) {
    asm volatile("ldmatrix.sync.aligned.m8n8.x4.shared.b16 {%0,%1,%2,%3}, [%4];"
                 : "=r"(r[0]), "=r"(r[1]), "=r"(r[2]), "=r"(r[3]) : "r"(a));
}
static __device__ __forceinline__ void mma_bf16(float* c, const u32* a, const u32* b) {
    asm volatile("mma.sync.aligned.m16n8k16.row.col.f32.bf16.bf16.f32 "
                 "{%0,%1,%2,%3}, {%4,%5,%6,%7}, {%8,%9}, {%0,%1,%2,%3};"
                 : "+f"(c[0]), "+f"(c[1]), "+f"(c[2]), "+f"(c[3])
                 : "r"(a[0]), "r"(a[1]), "r"(a[2]), "r"(a[3]), "r"(b[0]), "r"(b[1]));
}

// ---------------- W pre-split kernel ----------------
__global__ void prep_w(const float* __restrict__ W) {
    int p = blockIdx.x * blockDim.x + threadIdx.x;   // pair index, 65536 total
    float2 xy = ((const float2*)W)[p];
    u32 h = cvt_bf2(xy.x, xy.y);
    float h0 = __uint_as_float(h << 16);
    float h1 = __uint_as_float(h & 0xffff0000u);
    u32 l = cvt_bf2(xy.x - h0, xy.y - h1);
    g_Whi[p] = h;
    g_Wlo[p] = l;
}

// ---------------- exact fp32 rescoring ----------------
__device__ __noinline__ float exact_dot(const float* __restrict__ xr, const float* __restrict__ wr) {
    float a0 = 0.f, a1 = 0.f, a2 = 0.f, a3 = 0.f;
    for (int k = 0; k < KDIM; k += 4) {
        a0 = fmaf(__ldg(xr + k + 0), __ldg(wr + k + 0), a0);
        a1 = fmaf(__ldg(xr + k + 1), __ldg(wr + k + 1), a1);
        a2 = fmaf(__ldg(xr + k + 2), __ldg(wr + k + 2), a2);
        a3 = fmaf(__ldg(xr + k + 3), __ldg(wr + k + 3), a3);
    }
    return (a0 + a1) + (a2 + a3);
}

// ---------------- main kernel ----------------
__global__ __launch_bounds__(256, 1)
void router_mma(const float* __restrict__ x,
                const float* __restrict__ W,
                const float* __restrict__ bias,
                float* __restrict__ out)
{
    extern __shared__ __align__(16) char dsmp[];
    const u32 sb = smem_u32(dsmp);
    __shared__ float s_bias[NEXP];

    const int tid  = threadIdx.x;
    const int wid  = tid >> 5;
    const int lane = tid & 31;
    const int wm   = wid & 3;          // M block (32 tokens)
    const int wn   = wid >> 2;         // N block (32 experts)
    const int tokBase = blockIdx.x * TM;

    if (tid < NEXP) s_bias[tid] = bias[tid];

    float acc[2][4][4];
#pragma unroll
    for (int i = 0; i < 2; i++)
#pragma unroll
        for (int j = 0; j < 4; j++)
#pragma unroll
            for (int q = 0; q < 4; q++) acc[i][j][q] = 0.f;

    // register prefetch buffers
    float4 px[8];
    uint4  pwh[2], pwl[2];

    const float4* xp = (const float4*)x;
    const uint4* whp = (const uint4*)g_Whi;
    const uint4* wlp = (const uint4*)g_Wlo;

#define LOAD_CHUNK(c)                                                              \
    {                                                                              \
        _Pragma("unroll")                                                          \
        for (int r = 0; r < 8; r++) {                                              \
            int s = tid + 256 * r, row = s >> 4, c4 = s & 15;                      \
            px[r] = xp[(size_t)(tokBase + row) * (KDIM / 4) + (c) * 16 + c4];      \
        }                                                                          \
        _Pragma("unroll")                                                          \
        for (int r = 0; r < 2; r++) {                                              \
            int s = tid + 256 * r, row = s >> 3, c16 = s & 7;                      \
            int idx = row * (KDIM / 8) + (c) * 8 + c16;                            \
            pwh[r] = whp[idx];                                                     \
            pwl[r] = wlp[idx];                                                     \
        }                                                                          \
    }

    // ldmatrix addresses (chunk-invariant parts)
    // A (non-trans x4): lanes 0-15 -> rows(token) 0-15 (matrices 0,1), lanes 16-31 -> +16B (k+8)
    const u32 aAddr = sb + (u32)((wm * 32 + (lane & 15)) * SA + (lane >> 4) * 16);
    // B (non-trans x4): K-major [expert][k] tile, same orientation as A.
    //   lanes 0-7: n0-7 k0-7 | lanes 8-15: n0-7 k8-15 | lanes 16-23: n8-15 k0-7 | lanes 24-31: n8-15 k8-15
    const u32 bAddr = sb + OFF_BH +
        (u32)((wn * 32 + ((lane >> 4) & 1) * 8 + (lane & 7)) * SA + ((lane >> 3) & 1) * 16);

    LOAD_CHUNK(0);

    for (int c = 0; c < NCHUNK; c++) {
        // ---- convert + store x tile (hi/lo) ----
#pragma unroll
        for (int r = 0; r < 8; r++) {
            int s = tid + 256 * r, row = s >> 4, c4 = s & 15;
            u32 a = sb + (u32)(row * SA + c4 * 8);
            float4 v = px[r];
            u32 h01 = cvt_bf2(v.x, v.y), h23 = cvt_bf2(v.z, v.w);
            float g0 = __uint_as_float(h01 << 16), g1 = __uint_as_float(h01 & 0xffff0000u);
            float g2 = __uint_as_float(h23 << 16), g3 = __uint_as_float(h23 & 0xffff0000u);
            u32 l01 = cvt_bf2(v.x - g0, v.y - g1), l23 = cvt_bf2(v.z - g2, v.w - g3);
            sts64(a, h01, h23);
            sts64(a + OFF_AL, l01, l23);
        }
        // ---- store W tile (already bf16) ----
#pragma unroll
        for (int r = 0; r < 2; r++) {
            int s = tid + 256 * r, row = s >> 3, c16 = s & 7;
            u32 a = sb + OFF_BH + (u32)(row * SA + c16 * 16);
            sts128(a, pwh[r]);
            sts128(a + (OFF_BL - OFF_BH), pwl[r]);
        }
        __syncthreads();

        if (c + 1 < NCHUNK) LOAD_CHUNK(c + 1);   // issue global loads; latency hidden by compute

        // ---- compute: 4 k16 steps, 3 products (hh, hl, lh) ----
#pragma unroll
        for (int ks = 0; ks < 4; ks++) {
            const u32 kb = ks * 32;
            u32 Ah[2][4], Al[2][4], Bh[2][4], Bl[2][4];
#pragma unroll
            for (int mt = 0; mt < 2; mt++) {
                ldm_x4(Ah[mt], aAddr + mt * (16 * SA) + kb);
                ldm_x4(Al[mt], aAddr + OFF_AL + mt * (16 * SA) + kb);
            }
#pragma unroll
            for (int ng = 0; ng < 2; ng++) {
                ldm_x4(Bh[ng], bAddr + ng * (16 * SA) + kb);
                ldm_x4(Bl[ng], bAddr + (OFF_BL - OFF_BH) + ng * (16 * SA) + kb);
            }
#pragma unroll
            for (int mt = 0; mt < 2; mt++)
#pragma unroll
                for (int nt = 0; nt < 4; nt++) {
                    const u32* bh = &Bh[nt >> 1][(nt & 1) * 2];
                    const u32* bl = &Bl[nt >> 1][(nt & 1) * 2];
                    mma_bf16(acc[mt][nt], Ah[mt], bh);
                    mma_bf16(acc[mt][nt], Ah[mt], bl);
                    mma_bf16(acc[mt][nt], Al[mt], bh);
                }
        }
        __syncthreads();
    }

    // ---------------- epilogue ----------------
    float* ls = (float*)dsmp;            // logits staging [128][65]; stage region is dead
#pragma unroll
    for (int mt = 0; mt < 2; mt++)
#pragma unroll
        for (int nt = 0; nt < 4; nt++) {
            const int row = wm * 32 + mt * 16 + (lane >> 2);
            const int col = wn * 32 + nt * 8 + (lane & 3) * 2;
            ls[row * 65 + col]           = acc[mt][nt][0] + s_bias[col];
            ls[row * 65 + col + 1]       = acc[mt][nt][1] + s_bias[col + 1];
            ls[(row + 8) * 65 + col]     = acc[mt][nt][2] + s_bias[col];
            ls[(row + 8) * 65 + col + 1] = acc[mt][nt][3] + s_bias[col + 1];
        }
    __syncthreads();

    float* probs_out  = out;
    float* idx_out    = out + (size_t)TOKENS * 2;
    float* logits_out = out + (size_t)TOKENS * 4;

    // coalesced logits store: 2048 float4 per block, 8 per thread
#pragma unroll
    for (int r = 0; r < 8; r++) {
        int s  = tid + 256 * r;
        int t  = s >> 4;
        int e4 = s & 15;
        const float* lr = &ls[t * 65 + e4 * 4];
        *(float4*)(logits_out + (size_t)(tokBase + t) * NEXP + e4 * 4) =
            make_float4(lr[0], lr[1], lr[2], lr[3]);
    }

    // top-2 + softmax (+ exact rescue) : one thread per token
    if (tid < TM) {
        const int t = tid;
        const int gt = tokBase + t;
        const float* lr = &ls[t * 65];
        float m1 = -INFINITY, m2 = -INFINITY, m3 = -INFINITY;
        int i1 = 0, i2 = 0;
#pragma unroll
        for (int e = 0; e < NEXP; e++) {
            const float v = lr[e];
            if (v > m1)      { m3 = m2; m2 = m1; i2 = i1; m1 = v; i1 = e; }
            else if (v > m2) { m3 = m2; m2 = v; i2 = e; }
            else if (v > m3) { m3 = v; }
        }
        float p1v = m1, p2v = m2;

        if ((m1 - m2 < RESCUE_TH) || (m2 - m3 < RESCUE_TH)) {
            const float thr = m2 - RESCUE_TH;
            float e1 = -INFINITY, e2 = -INFINITY;
            int j1 = 0, j2 = 0;
            const float* xr = x + (size_t)gt * KDIM;
#pragma unroll 1
            for (int e = 0; e < NEXP; e++) {
                if (lr[e] > thr) {
                    float ex = exact_dot(xr, W + (size_t)e * KDIM) + s_bias[e];
                    if (ex > e1)      { e2 = e1; j2 = j1; e1 = ex; j1 = e; }
                    else if (ex > e2) { e2 = ex; j2 = e; }
                }
            }
            i1 = j1; i2 = j2; p1v = e1; p2v = e2;
        }

        const float ex2 = expf(p2v - p1v);
        const float inv = 1.0f / (1.0f + ex2);
        probs_out[gt * 2 + 0] = inv;
        probs_out[gt * 2 + 1] = ex2 * inv;
        idx_out[gt * 2 + 0] = (float)i1;
        idx_out[gt * 2 + 1] = (float)i2;
    }
}

extern "C" void kernel_launch(void* const* d_in, const int* in_sizes, int n_in,
                              void* d_out, int out_size)
{
    const float* x = (const float*)d_in[0];
    const float* W = (const float*)d_in[1];
    const float* b = (const float*)d_in[2];
    float* out = (float*)d_out;

    cudaFuncSetAttribute(router_mma, cudaFuncAttributeMaxDynamicSharedMemorySize, DYN_SMEM);
    prep_w<<<256, 256>>>(W);
    router_mma<<<TOKENS / TM, 256, DYN_SMEM>>>(x, W, b, out);
}

// round 5
// speedup vs baseline: 1.6560x; 1.0219x over previous
#include <cuda_runtime.h>
#include <cstdint>
#include <math.h>

#define TOKENS 16384
#define KDIM   2048
#define NEXP   64
#define TM     128
#define KC     64                      // K elems per chunk
#define NCHUNK (KDIM / KC)             // 32
#define SA     144                     // smem row stride bytes (conflict-free ldmatrix)
#define OFF_AL (128 * SA)              // 18432
#define OFF_BH (2 * 128 * SA)          // 36864
#define OFF_BL (2 * 128 * SA + 64 * SA)// 46080
#define STAGE  (2 * 128 * SA + 2 * 64 * SA)   // 55296 per stage
#define DYN_SMEM (2 * STAGE)                  // 110592, double-buffered
#define RESCUE_TH 3e-4f

typedef unsigned int u32;

// Pre-split W planes (bf16 pairs packed in u32), written by prep kernel each call.
__device__ __align__(16) u32 g_Whi[NEXP * KDIM / 2];
__device__ __align__(16) u32 g_Wlo[NEXP * KDIM / 2];

// ---------------- helpers ----------------
static __device__ __forceinline__ u32 smem_u32(const void* p) {
    u32 a;
    asm("{ .reg .u64 t; cvta.to.shared.u64 t, %1; cvt.u32.u64 %0, t; }" : "=r"(a) : "l"(p));
    return a;
}
static __device__ __forceinline__ u32 cvt_bf2(float f0, float f1) {
    u32 r;
    asm("cvt.rn.bf16x2.f32 %0, %1, %2;" : "=r"(r) : "f"(f1), "f"(f0));
    return r;
}
static __device__ __forceinline__ void sts64(u32 a, u32 lo, u32 hi) {
    asm volatile("st.shared.v2.b32 [%0], {%1,%2};" :: "r"(a), "r"(lo), "r"(hi) : "memory");
}
static __device__ __forceinline__ void cpasync16(u32 dst, const void* src) {
    asm volatile("cp.async.cg.shared.global [%0], [%1], 16;" :: "r"(dst), "l"(src) : "memory");
}
#define CP_COMMIT() asm volatile("cp.async.commit_group;" ::: "memory")
#define CP_WAIT0()  asm volatile("cp.async.wait_group 0;" ::: "memory")
static __device__ __forceinline__ void ldm_x4(u32* r, u32 a) {
    asm volatile("ldmatrix.sync.aligned.m8n8.x4.shared.b16 {%0,%1,%2,%3}, [%4];"
                 : "=r"(r[0]), "=r"(r[1]), "=r"(r[2]), "=r"(r[3]) : "r"(a));
}
static __device__ __forceinline__ void mma_bf16(float* c, const u32* a, const u32* b) {
    asm volatile("mma.sync.aligned.m16n8k16.row.col.f32.bf16.bf16.f32 "
                 "{%0,%1,%2,%3}, {%4,%5,%6,%7}, {%8,%9}, {%0,%1,%2,%3};"
                 : "+f"(c[0]), "+f"(c[1]), "+f"(c[2]), "+f"(c[3])
                 : "r"(a[0]), "r"(a[1]), "r"(a[2]), "r"(a[3]), "r"(b[0]), "r"(b[1]));
}

// ---------------- W pre-split kernel ----------------
__global__ void prep_w(const float* __restrict__ W) {
    int p = blockIdx.x * blockDim.x + threadIdx.x;   // pair index, 65536 total
    float2 xy = ((const float2*)W)[p];
    u32 h = cvt_bf2(xy.x, xy.y);
    float h0 = __uint_as_float(h << 16);
    float h1 = __uint_as_float(h & 0xffff0000u);
    u32 l = cvt_bf2(xy.x - h0, xy.y - h1);
    g_Whi[p] = h;
    g_Wlo[p] = l;
}

// ---------------- exact fp32 rescoring ----------------
__device__ __noinline__ float exact_dot(const float* __restrict__ xr, const float* __restrict__ wr) {
    float a0 = 0.f, a1 = 0.f, a2 = 0.f, a3 = 0.f;
    for (int k = 0; k < KDIM; k += 4) {
        a0 = fmaf(__ldg(xr + k + 0), __ldg(wr + k + 0), a0);
        a1 = fmaf(__ldg(xr + k + 1), __ldg(wr + k + 1), a1);
        a2 = fmaf(__ldg(xr + k + 2), __ldg(wr + k + 2), a2);
        a3 = fmaf(__ldg(xr + k + 3), __ldg(wr + k + 3), a3);
    }
    return (a0 + a1) + (a2 + a3);
}

// ---------------- main kernel ----------------
__global__ __launch_bounds__(256, 1)
void router_mma(const float* __restrict__ x,
                const float* __restrict__ W,
                const float* __restrict__ bias,
                float* __restrict__ out)
{
    extern __shared__ __align__(16) char dsmp[];
    const u32 sb = smem_u32(dsmp);
    __shared__ float s_bias[NEXP];

    const int tid  = threadIdx.x;
    const int wid  = tid >> 5;
    const int lane = tid & 31;
    const int wm   = wid & 3;          // M block (32 tokens)
    const int wn   = wid >> 2;         // N block (32 experts)
    const int tokBase = blockIdx.x * TM;

    if (tid < NEXP) s_bias[tid] = bias[tid];

    float acc[2][4][4];
#pragma unroll
    for (int i = 0; i < 2; i++)
#pragma unroll
        for (int j = 0; j < 4; j++)
#pragma unroll
            for (int q = 0; q < 4; q++) acc[i][j][q] = 0.f;

    float4 px[8];                       // x prefetch (single-buffered)
    const float4* xp = (const float4*)x;
    const uint4* whp = (const uint4*)g_Whi;
    const uint4* wlp = (const uint4*)g_Wlo;

    // thread's fixed load mapping
    const int xrow = tid >> 4, xc4 = tid & 15;        // + r*16 rows
    const int brow0 = tid >> 3, bc16 = tid & 7;       // rows tid>>3 and +32

#define LOAD_PX(c)                                                                  \
    {                                                                               \
        _Pragma("unroll")                                                           \
        for (int r = 0; r < 8; r++)                                                 \
            px[r] = xp[(size_t)(tokBase + xrow + r * 16) * (KDIM / 4) + (c) * 16 + xc4]; \
    }

#define ISSUE_B(c, st)                                                              \
    {                                                                               \
        _Pragma("unroll")                                                           \
        for (int r = 0; r < 2; r++) {                                               \
            int row = brow0 + r * 32;                                               \
            u32 d = sb + (st) * STAGE + OFF_BH + (u32)(row * SA + bc16 * 16);       \
            int idx = row * (KDIM / 8) + (c) * 8 + bc16;                            \
            cpasync16(d, whp + idx);                                                \
            cpasync16(d + (OFF_BL - OFF_BH), wlp + idx);                            \
        }                                                                           \
        CP_COMMIT();                                                                \
    }

#define STS_A(st)                                                                   \
    {                                                                               \
        _Pragma("unroll")                                                           \
        for (int r = 0; r < 8; r++) {                                               \
            u32 a = sb + (st) * STAGE + (u32)((xrow + r * 16) * SA + xc4 * 8);      \
            float4 v = px[r];                                                       \
            u32 h01 = cvt_bf2(v.x, v.y), h23 = cvt_bf2(v.z, v.w);                   \
            float g0 = __uint_as_float(h01 << 16), g1 = __uint_as_float(h01 & 0xffff0000u); \
            float g2 = __uint_as_float(h23 << 16), g3 = __uint_as_float(h23 & 0xffff0000u); \
            u32 l01 = cvt_bf2(v.x - g0, v.y - g1), l23 = cvt_bf2(v.z - g2, v.w - g3);       \
            sts64(a, h01, h23);                                                     \
            sts64(a + OFF_AL, l01, l23);                                            \
        }                                                                           \
    }

    // ldmatrix base addresses (per stage)
    const u32 aOff = (u32)((wm * 32 + (lane & 15)) * SA + (lane >> 4) * 16);
    const u32 bOff = (u32)(OFF_BH + (wn * 32 + ((lane >> 4) & 1) * 8 + (lane & 7)) * SA +
                           ((lane >> 3) & 1) * 16);

    // ---------------- prologue ----------------
    ISSUE_B(0, 0);
    LOAD_PX(0);
    STS_A(0);            // stalls on px(0) DRAM latency once
    LOAD_PX(1);

    // ---------------- pipelined main loop ----------------
    for (int c = 0; c < NCHUNK; c++) {
        const int cur = c & 1, nxt = cur ^ 1;
        CP_WAIT0();                       // B(c) landed
        __syncthreads();                  // A(c)+B(c) visible; stage 'nxt' free

        if (c + 1 < NCHUNK) ISSUE_B(c + 1, nxt);

        // ---- compute chunk c from stage cur ----
        const u32 aAddr = sb + cur * STAGE + aOff;
        const u32 bAddr = sb + cur * STAGE + bOff;
#pragma unroll
        for (int ks = 0; ks < 4; ks++) {
            const u32 kb = ks * 32;
            u32 Ah[2][4], Al[2][4], Bh[2][4], Bl[2][4];
#pragma unroll
            for (int mt = 0; mt < 2; mt++) {
                ldm_x4(Ah[mt], aAddr + mt * (16 * SA) + kb);
                ldm_x4(Al[mt], aAddr + OFF_AL + mt * (16 * SA) + kb);
            }
#pragma unroll
            for (int ng = 0; ng < 2; ng++) {
                ldm_x4(Bh[ng], bAddr + ng * (16 * SA) + kb);
                ldm_x4(Bl[ng], bAddr + (OFF_BL - OFF_BH) + ng * (16 * SA) + kb);
            }
#pragma unroll
            for (int mt = 0; mt < 2; mt++)
#pragma unroll
                for (int nt = 0; nt < 4; nt++) {
                    const u32* bh = &Bh[nt >> 1][(nt & 1) * 2];
                    const u32* bl = &Bl[nt >> 1][(nt & 1) * 2];
                    mma_bf16(acc[mt][nt], Ah[mt], bh);
                    mma_bf16(acc[mt][nt], Ah[mt], bl);
                    mma_bf16(acc[mt][nt], Al[mt], bh);
                }
        }

        if (c + 1 < NCHUNK) STS_A(nxt);   // px(c+1) landed during compute
        if (c + 2 < NCHUNK) LOAD_PX(c + 2); // px regs free after STS
    }

    // ---------------- epilogue ----------------
    __syncthreads();                      // all compute done; stage mem reusable
    float* ls = (float*)dsmp;             // logits staging [128][65]
#pragma unroll
    for (int mt = 0; mt < 2; mt++)
#pragma unroll
        for (int nt = 0; nt < 4; nt++) {
            const int row = wm * 32 + mt * 16 + (lane >> 2);
            const int col = wn * 32 + nt * 8 + (lane & 3) * 2;
            ls[row * 65 + col]           = acc[mt][nt][0] + s_bias[col];
            ls[row * 65 + col + 1]       = acc[mt][nt][1] + s_bias[col + 1];
            ls[(row + 8) * 65 + col]     = acc[mt][nt][2] + s_bias[col];
            ls[(row + 8) * 65 + col + 1] = acc[mt][nt][3] + s_bias[col + 1];
        }
    __syncthreads();

    float* probs_out  = out;
    float* idx_out    = out + (size_t)TOKENS * 2;
    float* logits_out = out + (size_t)TOKENS * 4;

    // coalesced logits store
#pragma unroll
    for (int r = 0; r < 8; r++) {
        int s  = tid + 256 * r;
        int t  = s >> 4;
        int e4 = s & 15;
        const float* lr = &ls[t * 65 + e4 * 4];
        *(float4*)(logits_out + (size_t)(tokBase + t) * NEXP + e4 * 4) =
            make_float4(lr[0], lr[1], lr[2], lr[3]);
    }

    // top-2 + softmax (+ exact rescue)
    if (tid < TM) {
        const int t = tid;
        const int gt = tokBase + t;
        const float* lr = &ls[t * 65];
        float m1 = -INFINITY, m2 = -INFINITY, m3 = -INFINITY;
        int i1 = 0, i2 = 0;
#pragma unroll
        for (int e = 0; e < NEXP; e++) {
            const float v = lr[e];
            if (v > m1)      { m3 = m2; m2 = m1; i2 = i1; m1 = v; i1 = e; }
            else if (v > m2) { m3 = m2; m2 = v; i2 = e; }
            else if (v > m3) { m3 = v; }
        }
        float p1v = m1, p2v = m2;

        if ((m1 - m2 < RESCUE_TH) || (m2 - m3 < RESCUE_TH)) {
            const float thr = m2 - RESCUE_TH;
            float e1 = -INFINITY, e2 = -INFINITY;
            int j1 = 0, j2 = 0;
            const float* xr = x + (size_t)gt * KDIM;
#pragma unroll 1
            for (int e = 0; e < NEXP; e++) {
                if (lr[e] > thr) {
                    float ex = exact_dot(xr, W + (size_t)e * KDIM) + s_bias[e];
                    if (ex > e1)      { e2 = e1; j2 = j1; e1 = ex; j1 = e; }
                    else if (ex > e2) { e2 = ex; j2 = e; }
                }
            }
            i1 = j1; i2 = j2; p1v = e1; p2v = e2;
        }

        const float ex2 = expf(p2v - p1v);
        const float inv = 1.0f / (1.0f + ex2);
        probs_out[gt * 2 + 0] = inv;
        probs_out[gt * 2 + 1] = ex2 * inv;
        idx_out[gt * 2 + 0] = (float)i1;
        idx_out[gt * 2 + 1] = (float)i2;
    }
}

extern "C" void kernel_launch(void* const* d_in, const int* in_sizes, int n_in,
                              void* d_out, int out_size)
{
    const float* x = (const float*)d_in[0];
    const float* W = (const float*)d_in[1];
    const float* b = (const float*)d_in[2];
    float* out = (float*)d_out;

    cudaFuncSetAttribute(router_mma, cudaFuncAttributeMaxDynamicSharedMemorySize, DYN_SMEM);
    prep_w<<<256, 256>>>(W);
    router_mma<<<TOKENS / TM, 256, DYN_SMEM>>>(x, W, b, out);
}